// round 8
// baseline (speedup 1.0000x reference)
#include <cuda_runtime.h>
#include <math.h>
#include <stdint.h>

// ====================================================================
// PulseTrainSynth — R7
//   prep  -> scan (blocks 0,1) + setup (block 2) +
//            noise dot partials over 128 blocks (4 band-groups x 32)
//   main  -> harmonic bank, ILP-2, grid.z=4 (2 cylinders per block),
//            half-bank partial rows; noise = sum of 4 partials
//   reso  -> persistent kernel; pass0 a/b fuses half-bank pair sums
// ====================================================================

#define T_LEN 65536
#define NCHN 8
#define NHARM 64
#define NBANDS 32
#define TWO_PI_F 6.283185307179586f

#define CHUNK 2048
#define HALOMAX 8192
#define RES_THREADS 512
#define RES_BLOCKS 128
#define MAXTAPS 100

__device__ float g_phase[2 * T_LEN];
__device__ float g_noisep[4][2 * T_LEN];
__device__ float g_v0[8 * T_LEN];     // main writes 8 half-bank rows: b*4+z
__device__ float g_v1[4 * T_LEN];
__device__ float g_vc0[2 * T_LEN];
__device__ float g_vc1[2 * T_LEN];

__device__ float g_pcoef[3][4][MAXTAPS];
__device__ int   g_pdel[3][4][MAXTAPS];
__device__ int   g_phalo[3][4];

__device__ unsigned g_bar_count = 0;
__device__ unsigned g_bar_gen   = 0;

__constant__ int   c_pcnt[4] = {9, 27, 99, 65};
__constant__ float c_forder[8] = {0.f, 4.f, 3.f, 7.f, 5.f, 2.f, 6.f, 1.f};

// ------------------------- threefry2x32-20 --------------------------
__device__ __forceinline__ void threefry2x32(uint32_t k0, uint32_t k1,
                                             uint32_t c0, uint32_t c1,
                                             uint32_t* o0, uint32_t* o1)
{
    uint32_t ks2 = k0 ^ k1 ^ 0x1BD11BDAu;
    uint32_t x0 = c0 + k0;
    uint32_t x1 = c1 + k1;
#define TF_R(r) { x0 += x1; x1 = (x1 << (r)) | (x1 >> (32 - (r))); x1 ^= x0; }
    TF_R(13) TF_R(15) TF_R(26) TF_R(6)   x0 += k1;  x1 += ks2 + 1u;
    TF_R(17) TF_R(29) TF_R(16) TF_R(24)  x0 += ks2; x1 += k0 + 2u;
    TF_R(13) TF_R(15) TF_R(26) TF_R(6)   x0 += k0;  x1 += k1 + 3u;
    TF_R(17) TF_R(29) TF_R(16) TF_R(24)  x0 += k1;  x1 += ks2 + 4u;
    TF_R(13) TF_R(15) TF_R(26) TF_R(6)   x0 += ks2; x1 += k0 + 5u;
#undef TF_R
    *o0 = x0; *o1 = x1;
}

__device__ __forceinline__ float jax_gumbel(uint32_t k0, uint32_t k1, int i)
{
    uint32_t o0, o1;
    threefry2x32(k0, k1, 0u, (uint32_t)i, &o0, &o1);
    uint32_t bits = o0 ^ o1;
    float f = __uint_as_float((bits >> 9) | 0x3F800000u) - 1.0f;  // [0,1)
    const float tiny = 1.17549435e-38f;
    float u = fmaxf(tiny, f);
    return -logf(-logf(u));
}

// --------------- prep: scan + setup + noise (one grid) --------------
__global__ void __launch_bounds__(1024) prep_kernel(const float* __restrict__ f0,
    const float* __restrict__ nba, const float* __restrict__ nb,
    const float* __restrict__ logit_a, const float* __restrict__ fbg_a, const float* __restrict__ refl_a,
    const float* __restrict__ logit_b, const float* __restrict__ fbg_b, const float* __restrict__ refl_b,
    const float* __restrict__ logit_c, const float* __restrict__ fbg_c, const float* __restrict__ refl_c)
{
    int tid = threadIdx.x;               // 1024 threads
    int lane = tid & 31, wid = tid >> 5;

    if (blockIdx.x >= 3) {
        // -------- noise dot partials: 4 band-groups x 32 blocks -----
        int k  = blockIdx.x - 3;                // 0..127
        int gb = k >> 5;                        // band group 0..3
        int v4 = (k & 31) * 1024 + tid;         // 0..32767
        int b  = v4 >> 14;
        int tq = v4 & 16383;
        const float4* nba4 = (const float4*)nba;
        const float4* nb4  = (const float4*)nb;
        float4 acc = make_float4(0.f, 0.f, 0.f, 0.f);
        #pragma unroll
        for (int m = 0; m < 8; m++) {
            int n = gb * 8 + m;
            float4 a = nba4[((size_t)(b * NBANDS + n) * T_LEN >> 2) + tq];
            float4 w = nb4[((size_t)n * T_LEN >> 2) + tq];
            acc.x = fmaf(a.x, w.x, acc.x);
            acc.y = fmaf(a.y, w.y, acc.y);
            acc.z = fmaf(a.z, w.z, acc.z);
            acc.w = fmaf(a.w, w.w, acc.w);
        }
        ((float4*)g_noisep[gb])[((size_t)b * T_LEN >> 2) + tq] = acc;
        return;
    }

    if (blockIdx.x < 2) {
        // ----- phase prefix sum: fp32 inner (reload), fp64 cross ----
        int b = blockIdx.x;
        const float4* f4 = (const float4*)(f0 + (size_t)b * T_LEN);
        const int vbase = tid * 16;              // 16 float4 = 64 floats
        float s = 0.0f;
        #pragma unroll
        for (int i = 0; i < 16; i++) {
            float4 v = f4[vbase + i];
            s += (TWO_PI_F * v.x) / 48000.0f;
            s += (TWO_PI_F * v.y) / 48000.0f;
            s += (TWO_PI_F * v.z) / 48000.0f;
            s += (TWO_PI_F * v.w) / 48000.0f;
        }
        double inc = (double)s;
        #pragma unroll
        for (int off = 1; off < 32; off <<= 1) {
            double nv = __shfl_up_sync(0xffffffffu, inc, off);
            if (lane >= off) inc += nv;
        }
        __shared__ double wsums[32];
        if (lane == 31) wsums[wid] = inc;
        __syncthreads();
        if (wid == 0) {
            double w = wsums[lane];
            #pragma unroll
            for (int off = 1; off < 32; off <<= 1) {
                double nv = __shfl_up_sync(0xffffffffu, w, off);
                if (lane >= off) w += nv;
            }
            wsums[lane] = w;
        }
        __syncthreads();
        double base_d = inc - (double)s + (wid ? wsums[wid - 1] : 0.0); // exclusive
        float base_half = (float)(0.5 * base_d);
        float4* ph4 = (float4*)(g_phase + (size_t)b * T_LEN);
        float run = 0.0f;
        #pragma unroll
        for (int i = 0; i < 16; i++) {
            float4 v = f4[vbase + i];
            float p0 = run + (TWO_PI_F * v.x) / 48000.0f;
            float p1 = p0  + (TWO_PI_F * v.y) / 48000.0f;
            float p2 = p1  + (TWO_PI_F * v.z) / 48000.0f;
            float p3 = p2  + (TWO_PI_F * v.w) / 48000.0f;
            run = p3;
            float4 o;
            o.x = fmaf(0.5f, p0, base_half);
            o.y = fmaf(0.5f, p1, base_half);
            o.z = fmaf(0.5f, p2, base_half);
            o.w = fmaf(0.5f, p3, base_half);
            ph4[vbase + i] = o;
        }
        return;
    }

    // ------------------------- setup (block 2) ----------------------
    __shared__ uint32_t skey[3][2];
    __shared__ float rv[128];
    __shared__ int   ri[128];
    __shared__ int   s_idx[3];
    __shared__ int   sD1, sD2;
    __shared__ float P[10][65];   // A^1,A^2,A^3,A^4,A^8,A^12,A^16,A^32,A^48,A^64

    if (tid == 0) {
        for (int j = 0; j < 3; j++) {
            uint32_t o0, o1;
            threefry2x32(0u, 42u, 0u, (uint32_t)j, &o0, &o1);
            skey[j][0] = o0; skey[j][1] = o1;
        }
    }
    __syncthreads();

    const float* logits[3] = {logit_a, logit_b, logit_c};
    const float* refls[3]  = {refl_a, refl_b, refl_c};
    const float* fbs[3]    = {fbg_a, fbg_b, fbg_c};
    const int    Ls[3]     = {85, 85, 8};
    const int    mind[3]   = {40, 40, 32};

    for (int r = 0; r < 3; r++) {
        int L = Ls[r];
        if (tid < 128) {
            float score = -3.0e38f;
            if (tid < L)
                score = logits[r][tid] + jax_gumbel(skey[r][0], skey[r][1], tid);
            rv[tid] = score; ri[tid] = tid;
        }
        __syncthreads();
        for (int s = 64; s > 0; s >>= 1) {
            if (tid < s) {
                float ov = rv[tid + s]; int oi = ri[tid + s];
                if (ov > rv[tid] || (ov == rv[tid] && oi < ri[tid])) {
                    rv[tid] = ov; ri[tid] = oi;
                }
            }
            __syncthreads();
        }
        if (tid == 0) s_idx[r] = ri[0];
        __syncthreads();
    }

    const int psz[10] = {2, 3, 4, 5, 9, 13, 17, 33, 49, 65};
    const int plan[9][3] = {
        {1, 0, 0}, {2, 0, 1}, {3, 1, 1}, {4, 3, 3}, {5, 3, 4},
        {6, 4, 4}, {7, 6, 6}, {8, 6, 7}, {9, 7, 7},
    };
    const int js[4][3]      = {{1,2,3},{4,8,12},{16,32,48},{64,0,0}};
    const int nj[4]         = {3, 3, 3, 1};
    const int slotTab[4][3] = {{0,1,2},{3,4,5},{6,7,8},{9,9,9}};

    for (int r = 0; r < 3; r++) {
        if (tid == 0) {
            float r0 = refls[r][0], r1 = refls[r][1];
            if (r == 2) { r0 = 1.0f / (1.0f + expf(-r0)); r1 = 1.0f / (1.0f + expf(-r1)); }
            else        { r0 = tanhf(r0); r1 = tanhf(r1); }
            float k1v = tanhf(r0);
            float k2v = tanhf(r1);
            float a1 = k1v * (1.0f - k2v);
            float a2 = fminf(0.999f, fmaxf(-0.999f, k2v));
            float bnd = 0.999f - fabsf(a2);
            a1 = fminf(bnd, fmaxf(-bnd, a1));
            float g = powf(1.0f / (1.0f + expf(-fbs[r][0])), 0.45f);
            int L = Ls[r];
            int idx = s_idx[r];
            sD1 = mind[r] + idx + 1;
            sD2 = mind[r] + ((idx + 1) % L) + 1;
            P[0][0] = a1 * g; P[0][1] = a2 * g;
        }
        __syncthreads();

        for (int cv = 0; cv < 9; cv++) {
            int d = plan[cv][0], a = plan[cv][1], bb = plan[cv][2];
            int la = psz[a], lb = psz[bb], ld = la + lb - 1;
            if (tid < ld) {
                int i = tid;
                int lo = i - (lb - 1); if (lo < 0) lo = 0;
                int hi = (la - 1 < i) ? la - 1 : i;
                float s = 0.0f;
                for (int q = lo; q <= hi; q++) s += P[a][q] * P[bb][i - q];
                P[d][i] = s;
            }
            __syncthreads();
        }

        // ---- parallel tap-table fill (thread per tap) ----
        int D1 = sD1, D2 = sD2;
        #pragma unroll
        for (int p = 0; p < 4; p++) {
            int cnt = (p == 0) ? 9 : (p == 1 ? 27 : (p == 2 ? 99 : 65));
            if (tid < cnt) {
                int m = 0, bofs = 0;
                while (m < nj[p] - 1 && tid >= bofs + js[p][m] + 1) {
                    bofs += js[p][m] + 1; m++;
                }
                int j = js[p][m];
                int i = tid - bofs;
                float sgn = (j & 1) ? -1.0f : 1.0f;
                g_pcoef[r][p][tid] = sgn * P[slotTab[p][m]][i];
                g_pdel[r][p][tid]  = j * D1 + i * (D2 - D1);
            }
            if (tid == 0) {
                int jmax = js[p][nj[p] - 1];
                int maxD = (D1 > D2) ? D1 : D2;
                g_phalo[r][p] = (jmax * maxD + 511) & ~511;
            }
        }
        __syncthreads();
    }
}

// ------------------ main (ILP-2, 2 cylinders/block) -----------------
__global__ void __launch_bounds__(256) main_kernel(
                            const float* __restrict__ amps,
                            const float* __restrict__ fm_in,
                            const float* __restrict__ cps,
                            const float* __restrict__ nps,
                            const float* __restrict__ npg_in,
                            const float* __restrict__ fng_in)
{
    int b = blockIdx.y;
    int z = blockIdx.z;               // 0..3 : cylinders {2z, 2z+1}; bank = z>>1
    int t0 = blockIdx.x * 512 + threadIdx.x;   // second sample at t0+256
    size_t brow = (size_t)b * T_LEN;

    float bank[2], turb1[2], phase[2], fmv[2];
    #pragma unroll
    for (int u = 0; u < 2; u++) {
        int t = t0 + u * 256;
        size_t bt = brow + t;
        float ph    = g_phase[bt];
        float noise = g_noisep[0][bt] + g_noisep[1][bt]
                    + g_noisep[2][bt] + g_noisep[3][bt];
        float npg   = npg_in[bt];
        float fng   = fng_in[bt];
        turb1[u] = 1.0f + noise * (npg + fng) * 0.7f;
        phase[u] = ph;
        fmv[u]   = fm_in[bt];
        if ((z & 1) == 0) {
            float na  = nps[(size_t)(b * 2) * T_LEN + t];
            float nbv = nps[(size_t)(b * 2 + 1) * T_LEN + t];
            float nph = fmodf(ph, TWO_PI_F);
            float nenv = (1.0f - __expf(-na * nph)) * __expf(-nbv * nph);
            bank[u] = 4.0f * (noise * nenv * npg + noise * fng * 0.3f);
        } else {
            bank[u] = 0.0f;
        }
    }

    #pragma unroll 1
    for (int c2 = 0; c2 < 2; c2++) {
        int c = z * 2 + c2;
        float ang = c_forder[c] * (TWO_PI_F / 8.0f);
        const float* ap = amps + ((size_t)(b * NCHN + c) * NHARM) * T_LEN + t0;

        float cph[2], scur[2], sm1[2], twoC[2], acc[2];
        #pragma unroll
        for (int u = 0; u < 2; u++) {
            float cp = fmodf(phase[u] + ang, TWO_PI_F);
            float hp = __powf(cp * (1.0f / TWO_PI_F), fmv[u]) * TWO_PI_F;
            float sv, cv;
            sincosf(hp, &sv, &cv);
            cph[u] = cp; scur[u] = sv; sm1[u] = 0.0f;
            twoC[u] = 2.0f * cv; acc[u] = 0.0f;
        }

        #pragma unroll
        for (int h = 0; h < NHARM; h++) {
            #pragma unroll
            for (int u = 0; u < 2; u++) {
                acc[u] = fmaf(__ldcs(ap + (size_t)h * T_LEN + u * 256), scur[u], acc[u]);
                float snxt = fmaf(twoC[u], scur[u], -sm1[u]);
                sm1[u] = scur[u]; scur[u] = snxt;
            }
        }

        #pragma unroll
        for (int u = 0; u < 2; u++) {
            int t = t0 + u * 256;
            float alpha = cps[(size_t)(b * 16 + c) * T_LEN + t];
            float beta  = cps[(size_t)(b * 16 + 8 + c) * T_LEN + t];
            float env = (1.0f - __expf(-alpha * cph[u])) * __expf(-beta * cph[u]);
            bank[u] = fmaf(-acc[u] * env * 10.0f, turb1[u], bank[u]);
        }
    }

    #pragma unroll
    for (int u = 0; u < 2; u++)
        g_v0[(size_t)(b * 4 + z) * T_LEN + t0 + u * 256] = bank[u];
}

// ---------------- resonator: all passes, one kernel -----------------
__device__ __forceinline__ void grid_barrier()
{
    __syncthreads();
    if (threadIdx.x == 0) {
        __threadfence();
        unsigned gen = *((volatile unsigned*)&g_bar_gen);
        if (atomicAdd(&g_bar_count, 1u) == (unsigned)(RES_BLOCKS - 1)) {
            atomicExch(&g_bar_count, 0u);
            __threadfence();
            atomicAdd(&g_bar_gen, 1u);
        } else {
            while (*((volatile unsigned*)&g_bar_gen) == gen) __nanosleep(64);
        }
        __threadfence();
    }
    __syncthreads();
}

__device__ __forceinline__ void fir_stage(
    const float* __restrict__ in, float* __restrict__ out,
    int row, int chunk, int chain, int pass, int sumpair,
    float* sx, float* sc, int* sd)
{
    int tid = threadIdx.x;
    int cnt = c_pcnt[pass];
    int halo = g_phalo[chain][pass];

    for (int i = tid; i < cnt; i += RES_THREADS) {
        sc[i] = g_pcoef[chain][pass][i];
        sd[i] = g_pdel[chain][pass][i];
    }

    int base = chunk * CHUNK;
    int nload = halo + CHUNK;
    if (sumpair) {
        const float* xa = in + ((size_t)(2 * row)) * T_LEN;
        const float* xb = in + ((size_t)(2 * row + 1)) * T_LEN;
        for (int k = tid; k < nload; k += RES_THREADS) {
            int g = base - halo + k;
            sx[k] = (g >= 0) ? (xa[g] + xb[g]) : 0.0f;
        }
    } else {
        const float* x = in + (size_t)row * T_LEN;
        for (int k = tid; k < nload; k += RES_THREADS) {
            int g = base - halo + k;
            sx[k] = (g >= 0) ? x[g] : 0.0f;
        }
    }
    __syncthreads();

    #pragma unroll
    for (int o = 0; o < CHUNK / RES_THREADS; o++) {
        int li = o * RES_THREADS + tid;
        float acc = sx[halo + li];
        for (int i = 0; i < cnt; i++)
            acc = fmaf(sc[i], sx[halo + li - sd[i]], acc);
        out[(size_t)row * T_LEN + base + li] = acc;
    }
}

__global__ void __launch_bounds__(RES_THREADS) resonator_kernel(float* __restrict__ out)
{
    __shared__ float sx[HALOMAX + CHUNK];
    __shared__ float sc[MAXTAPS];
    __shared__ int   sd[MAXTAPS];

    int bid = blockIdx.x;                 // 0..127
    int row4 = bid >> 5;                  // 0..3 = b*2 + bank
    int chunk = bid & 31;                 // 0..31
    int chain_ab = row4 & 1;

    // pass0 a/b fuses half-bank partial rows 2*row4, 2*row4+1 of g_v0 (8 rows)
    fir_stage(g_v0, g_v1, row4, chunk, chain_ab, 0, 1, sx, sc, sd);
    grid_barrier();
    fir_stage(g_v1, g_v0, row4, chunk, chain_ab, 1, 0, sx, sc, sd);
    grid_barrier();
    fir_stage(g_v0, g_v1, row4, chunk, chain_ab, 2, 0, sx, sc, sd);
    grid_barrier();
    fir_stage(g_v1, g_v0, row4, chunk, chain_ab, 3, 0, sx, sc, sd);
    grid_barrier();

    // chain c: rows of g_v0 now 0=b0A,1=b0B,2=b1A,3=b1B; pass0 sums A+B
    int active = (bid < 64);
    int rowc = bid >> 5;
    if (active) fir_stage(g_v0, g_vc0, rowc, chunk, 2, 0, 1, sx, sc, sd);
    grid_barrier();
    if (active) fir_stage(g_vc0, g_vc1, rowc, chunk, 2, 1, 0, sx, sc, sd);
    grid_barrier();
    if (active) fir_stage(g_vc1, g_vc0, rowc, chunk, 2, 2, 0, sx, sc, sd);
    grid_barrier();
    if (active) fir_stage(g_vc0, out, rowc, chunk, 2, 3, 0, sx, sc, sd);
}

// ----------------------------- launch -------------------------------
extern "C" void kernel_launch(void* const* d_in, const int* in_sizes, int n_in,
                              void* d_out, int out_size)
{
    (void)in_sizes; (void)n_in; (void)out_size;
    const float* f0   = (const float*)d_in[0];
    const float* amps = (const float*)d_in[1];
    const float* fm   = (const float*)d_in[2];
    const float* cps  = (const float*)d_in[4];
    const float* nba  = (const float*)d_in[5];
    const float* nps  = (const float*)d_in[6];
    const float* npg  = (const float*)d_in[7];
    const float* fng  = (const float*)d_in[8];
    const float* nb   = (const float*)d_in[9];
    float* out = (float*)d_out;

    prep_kernel<<<131, 1024>>>(f0, nba, nb,
        (const float*)d_in[10], (const float*)d_in[11], (const float*)d_in[12],
        (const float*)d_in[13], (const float*)d_in[14], (const float*)d_in[15],
        (const float*)d_in[16], (const float*)d_in[17], (const float*)d_in[18]);

    dim3 gm(T_LEN / 512, 2, 4);
    main_kernel<<<gm, 256>>>(amps, fm, cps, nps, npg, fng);

    resonator_kernel<<<RES_BLOCKS, RES_THREADS>>>(out);
}